// round 10
// baseline (speedup 1.0000x reference)
#include <cuda_runtime.h>
#include <cuda_fp16.h>
#include <cstdint>
#include <cstdio>

// Problem constants
#define NB   4
#define LSEQ 8192
#define EMB  512
#define HEADS 8
#define HDIM 64
#define BS   128
#define ABLK 64
#define FFD  1024
#define MROWS (NB*LSEQ)  // 32768

// ---------------------------------------------------------------------------
// Scratch
// ---------------------------------------------------------------------------
__device__ __half h_val[MROWS * EMB];
__device__ __half h_key[MROWS * EMB];
__device__ __half h_qry[MROWS * EMB];
__device__ __half h_q  [MROWS * EMB];
__device__ __half h_k  [MROWS * EMB];
__device__ __half h_v  [MROWS * EMB];
__device__ __half h_att[MROWS * EMB];
__device__ __half h_x  [MROWS * EMB];
__device__ __half h_ff [MROWS * FFD];
__device__ __half h_t1 [MROWS * EMB];   // proj out (fp16)
__device__ __half h_t2 [MROWS * EMB];   // ff2 out (fp16)
// fp16 transposed weights (K-major [N][K])
__device__ __half g_wvt[EMB * EMB];
__device__ __half g_wkt[EMB * EMB];
__device__ __half g_wqt[EMB * EMB];
__device__ __half g_wot[EMB * EMB];
__device__ __half g_w1t[FFD * EMB];
__device__ __half g_w2t[EMB * FFD];

// ---------------------------------------------------------------------------
// helpers
// ---------------------------------------------------------------------------
__device__ __forceinline__ void cp16s(unsigned saddr, const void* src) {
    asm volatile("cp.async.cg.shared.global [%0], [%1], 16;" :: "r"(saddr), "l"(src));
}
#define CP_COMMIT() asm volatile("cp.async.commit_group;")
#define CP_WAIT0()  asm volatile("cp.async.wait_group 0;")
#define CP_WAIT1()  asm volatile("cp.async.wait_group 1;")

__device__ __forceinline__ unsigned smem_u32(const void* p) {
    return (unsigned)__cvta_generic_to_shared(p);
}

__device__ __forceinline__ void ldm_x4(uint32_t r[4], unsigned addr) {
    asm volatile("ldmatrix.sync.aligned.m8n8.x4.shared.b16 {%0,%1,%2,%3}, [%4];"
                 : "=r"(r[0]), "=r"(r[1]), "=r"(r[2]), "=r"(r[3]) : "r"(addr));
}
__device__ __forceinline__ void ldm_x4t(uint32_t r[4], unsigned addr) {
    asm volatile("ldmatrix.sync.aligned.m8n8.x4.trans.shared.b16 {%0,%1,%2,%3}, [%4];"
                 : "=r"(r[0]), "=r"(r[1]), "=r"(r[2]), "=r"(r[3]) : "r"(addr));
}

__device__ __forceinline__ void mma_f16(float c[4], const uint32_t a[4],
                                        const uint32_t b[2]) {
    asm volatile(
        "mma.sync.aligned.m16n8k16.row.col.f32.f16.f16.f32 "
        "{%0,%1,%2,%3}, {%4,%5,%6,%7}, {%8,%9}, {%0,%1,%2,%3};"
        : "+f"(c[0]), "+f"(c[1]), "+f"(c[2]), "+f"(c[3])
        : "r"(a[0]), "r"(a[1]), "r"(a[2]), "r"(a[3]), "r"(b[0]), "r"(b[1]));
}

__device__ __forceinline__ uint32_t pack2(float x, float y) {
    __half2 h = __floats2half2_rn(x, y);
    return *(uint32_t*)&h;
}

// ---------------------------------------------------------------------------
// FP16 tensor-core GEMM: CTA 128x128, 256 thr (8 warps 2x4), warp tile 64x32.
// BK=64 (SW128). 3-stage cp.async ring, one sync per chunk, 2 CTAs/SM.
// gridDim.z batches independent GEMMs (QKV).
// ---------------------------------------------------------------------------
#define HG_STAGE 32768
#define HG_SMEM  (3 * HG_STAGE)

struct GemmArgs {
    const __half* A[3];
    const __half* B[3];
    const float*  bias[3];
    void*         C[3];
};

template<int OUT_HALF, int DO_GELU>
__global__ __launch_bounds__(256, 2)
void hgemm(GemmArgs args, int M, int Nn, int K)
{
    extern __shared__ __align__(1024) char smem[];
    const unsigned sb = smem_u32(smem);

    const int z    = blockIdx.z;
    const int tid  = threadIdx.x;
    const int lane = tid & 31;
    const int warp = tid >> 5;
    const int wm   = warp >> 2;       // 0..1
    const int wn   = warp & 3;        // 0..3
    const int g    = lane >> 2;
    const int t    = lane & 3;

    const int m0 = blockIdx.y * 128;
    const int n0 = blockIdx.x * 128;
    const __half* Ag = args.A[z] + (size_t)m0 * K;
    const __half* Bg = args.B[z] + (size_t)n0 * K;
    const float* bias = args.bias[z];

    const unsigned rA = (unsigned)(wm * 64 + (lane & 7) + ((lane >> 3) & 1) * 8);
    const unsigned kgA0 = (unsigned)(lane >> 4);
    const unsigned rB = (unsigned)(wn * 32 + (lane & 7) + ((lane >> 4) & 1) * 8);
    const unsigned kgB0 = (unsigned)((lane >> 3) & 1);

    float acc[4][4][4];
    #pragma unroll
    for (int mt = 0; mt < 4; mt++)
        #pragma unroll
        for (int nt = 0; nt < 4; nt++)
            #pragma unroll
            for (int i = 0; i < 4; i++) acc[mt][nt][i] = 0.f;

    const int nCh = K / 64;

    auto load_chunk = [&](int s, int kc) {
        const unsigned sA = sb + s * HG_STAGE;
        const unsigned sB = sA + 16384;
        const __half* Ac = Ag + kc * 64;
        const __half* Bc = Bg + kc * 64;
        #pragma unroll
        for (int i = 0; i < 4; i++) {
            int id = tid + i * 256;          // 0..1023
            int r  = id >> 3;                // 0..127
            int kg = id & 7;
            unsigned off = (unsigned)(r * 128 + kg * 16);
            unsigned sw  = off ^ ((off >> 3) & 0x70);
            cp16s(sA + sw, Ac + (size_t)r * K + kg * 8);
            cp16s(sB + sw, Bc + (size_t)r * K + kg * 8);
        }
    };

    load_chunk(0, 0); CP_COMMIT();
    load_chunk(1, 1); CP_COMMIT();

    int s = 0;
    for (int c = 0; c < nCh; c++) {
        CP_WAIT1();
        __syncthreads();

        if (c + 2 < nCh) {
            int sn = s + 2; if (sn >= 3) sn -= 3;
            load_chunk(sn, c + 2);
        }
        CP_COMMIT();

        const unsigned sA = sb + s * HG_STAGE;
        const unsigned sB = sA + 16384;
        #pragma unroll
        for (int ks = 0; ks < 4; ks++) {
            uint32_t a[4][4];
            #pragma unroll
            for (int mt = 0; mt < 4; mt++) {
                unsigned r = rA + mt * 16;
                unsigned addr = sA + (r << 7) + ((((kgA0 + 2 * ks) ^ (r & 7))) << 4);
                ldm_x4(a[mt], addr);
            }
            uint32_t b[4][2];
            #pragma unroll
            for (int p = 0; p < 2; p++) {
                uint32_t r4[4];
                unsigned r = rB + p * 16;
                unsigned addr = sB + (r << 7) + ((((kgB0 + 2 * ks) ^ (r & 7))) << 4);
                ldm_x4(r4, addr);
                b[2*p][0]   = r4[0]; b[2*p][1]   = r4[1];
                b[2*p+1][0] = r4[2]; b[2*p+1][1] = r4[3];
            }
            #pragma unroll
            for (int mt = 0; mt < 4; mt++)
                #pragma unroll
                for (int nt = 0; nt < 4; nt++)
                    mma_f16(acc[mt][nt], a[mt], b[nt]);
        }

        if (++s >= 3) s = 0;
    }

    // epilogue
    #pragma unroll
    for (int nt = 0; nt < 4; nt++) {
        const int col = n0 + wn * 32 + nt * 8 + 2 * t;
        const float2 bv = *(const float2*)(bias + col);
        #pragma unroll
        for (int mt = 0; mt < 4; mt++) {
            const int row0 = m0 + wm * 64 + mt * 16 + g;
            const int row1 = row0 + 8;
            float v0 = acc[mt][nt][0] + bv.x;
            float v1 = acc[mt][nt][1] + bv.y;
            float v2 = acc[mt][nt][2] + bv.x;
            float v3 = acc[mt][nt][3] + bv.y;
            if (DO_GELU) {
                v0 = 0.5f * v0 * (1.f + erff(v0 * 0.70710678118654752f));
                v1 = 0.5f * v1 * (1.f + erff(v1 * 0.70710678118654752f));
                v2 = 0.5f * v2 * (1.f + erff(v2 * 0.70710678118654752f));
                v3 = 0.5f * v3 * (1.f + erff(v3 * 0.70710678118654752f));
            }
            if (OUT_HALF) {
                __half* C = (__half*)args.C[z];
                *(uint32_t*)(C + (size_t)row0 * Nn + col) = pack2(v0, v1);
                *(uint32_t*)(C + (size_t)row1 * Nn + col) = pack2(v2, v3);
            } else {
                float* C = (float*)args.C[z];
                *(float2*)(C + (size_t)row0 * Nn + col) = make_float2(v0, v1);
                *(float2*)(C + (size_t)row1 * Nn + col) = make_float2(v2, v3);
            }
        }
    }
}

// ---------------------------------------------------------------------------
// FP16 block-diagonal attention, FA-style; 2 CTAs/SM; V load overlaps QK^T.
// ---------------------------------------------------------------------------
#define ATT_SMEM (3 * 16384)

__global__ __launch_bounds__(256, 2)
void attn_h(const __half* __restrict__ Q, const __half* __restrict__ K,
            const __half* __restrict__ V, const int* __restrict__ mask,
            __half* __restrict__ O)
{
    extern __shared__ __align__(1024) char smem[];
    const unsigned sQ = smem_u32(smem);
    const unsigned sK = sQ + 16384;
    const unsigned sV = sK + 16384;

    const int h = blockIdx.x, a = blockIdx.y, n = blockIdx.z;
    const int tid  = threadIdx.x;
    const int lane = tid & 31;
    const int w    = tid >> 5;
    const int g    = lane >> 2;
    const int t    = lane & 3;
    const size_t base = ((size_t)n * LSEQ + (size_t)a * BS) * EMB + h * HDIM;

    // group 1: Q + K
    #pragma unroll
    for (int i = 0; i < 4; i++) {
        int id = tid + i * 256;
        int r  = id >> 3;
        int kg = id & 7;
        unsigned off = (unsigned)(r * 128 + kg * 16);
        unsigned sw  = off ^ ((off >> 3) & 0x70);
        const size_t go = base + (size_t)r * EMB + kg * 8;
        cp16s(sQ + sw, Q + go);
        cp16s(sK + sw, K + go);
    }
    CP_COMMIT();
    // group 2: V (overlaps QK^T compute)
    #pragma unroll
    for (int i = 0; i < 4; i++) {
        int id = tid + i * 256;
        int r  = id >> 3;
        int kg = id & 7;
        unsigned off = (unsigned)(r * 128 + kg * 16);
        unsigned sw  = off ^ ((off >> 3) & 0x70);
        cp16s(sV + sw, V + base + (size_t)r * EMB + kg * 8);
    }
    CP_COMMIT();

    CP_WAIT1();      // Q,K resident; V may still be in flight
    __syncthreads();

    float accs[16][4];
    #pragma unroll
    for (int nt = 0; nt < 16; nt++)
        #pragma unroll
        for (int i = 0; i < 4; i++) accs[nt][i] = 0.f;

    const unsigned rQ = (unsigned)(w * 16 + (lane & 7) + ((lane >> 3) & 1) * 8);
    const unsigned kgQ0 = (unsigned)(lane >> 4);
    const unsigned rK0 = (unsigned)((lane & 7) + ((lane >> 4) & 1) * 8);
    const unsigned kgK0 = (unsigned)((lane >> 3) & 1);

    #pragma unroll
    for (int ks = 0; ks < 4; ks++) {
        uint32_t aq[4];
        {
            unsigned addr = sQ + (rQ << 7) + ((((kgQ0 + 2 * ks) ^ (rQ & 7))) << 4);
            ldm_x4(aq, addr);
        }
        #pragma unroll
        for (int p = 0; p < 8; p++) {
            uint32_t r4[4];
            unsigned rKp = rK0 + p * 16;
            unsigned addr = sK + (rKp << 7) + ((((kgK0 + 2 * ks) ^ (rKp & 7))) << 4);
            ldm_x4(r4, addr);
            uint32_t b0[2] = { r4[0], r4[1] };
            uint32_t b1[2] = { r4[2], r4[3] };
            mma_f16(accs[2*p],   aq, b0);
            mma_f16(accs[2*p+1], aq, b1);
        }
    }

    const int* mrow = mask + n * (BS * BS);
    const int r0 = w * 16 + g;
    const int r1 = r0 + 8;
    float mx0 = -1e30f, mx1 = -1e30f;
    #pragma unroll
    for (int nt = 0; nt < 16; nt++) {
        const int c = 2 * t + 8 * nt;
        int2 m0v = *(const int2*)(mrow + (size_t)r0 * BS + c);
        int2 m1v = *(const int2*)(mrow + (size_t)r1 * BS + c);
        accs[nt][0] = m0v.x ? accs[nt][0] * 0.125f : -1e20f;
        accs[nt][1] = m0v.y ? accs[nt][1] * 0.125f : -1e20f;
        accs[nt][2] = m1v.x ? accs[nt][2] * 0.125f : -1e20f;
        accs[nt][3] = m1v.y ? accs[nt][3] * 0.125f : -1e20f;
        mx0 = fmaxf(mx0, fmaxf(accs[nt][0], accs[nt][1]));
        mx1 = fmaxf(mx1, fmaxf(accs[nt][2], accs[nt][3]));
    }
    #pragma unroll
    for (int off = 1; off <= 2; off <<= 1) {
        mx0 = fmaxf(mx0, __shfl_xor_sync(0xffffffffu, mx0, off));
        mx1 = fmaxf(mx1, __shfl_xor_sync(0xffffffffu, mx1, off));
    }
    float sum0 = 0.f, sum1 = 0.f;
    #pragma unroll
    for (int nt = 0; nt < 16; nt++) {
        accs[nt][0] = __expf(accs[nt][0] - mx0);
        accs[nt][1] = __expf(accs[nt][1] - mx0);
        accs[nt][2] = __expf(accs[nt][2] - mx1);
        accs[nt][3] = __expf(accs[nt][3] - mx1);
        sum0 += accs[nt][0] + accs[nt][1];
        sum1 += accs[nt][2] + accs[nt][3];
    }
    #pragma unroll
    for (int off = 1; off <= 2; off <<= 1) {
        sum0 += __shfl_xor_sync(0xffffffffu, sum0, off);
        sum1 += __shfl_xor_sync(0xffffffffu, sum1, off);
    }
    const float inv0 = 1.f / sum0;
    const float inv1 = 1.f / sum1;

    CP_WAIT0();      // V resident
    __syncthreads();

    float o[8][4];
    #pragma unroll
    for (int nt = 0; nt < 8; nt++)
        #pragma unroll
        for (int i = 0; i < 4; i++) o[nt][i] = 0.f;

    const unsigned rV0 = (unsigned)((lane & 7) + ((lane >> 3) & 1) * 8);
    const unsigned kgV0 = (unsigned)(lane >> 4);

    #pragma unroll
    for (int ks = 0; ks < 8; ks++) {
        uint32_t ap[4];
        ap[0] = pack2(accs[2*ks][0],   accs[2*ks][1]);
        ap[1] = pack2(accs[2*ks][2],   accs[2*ks][3]);
        ap[2] = pack2(accs[2*ks+1][0], accs[2*ks+1][1]);
        ap[3] = pack2(accs[2*ks+1][2], accs[2*ks+1][3]);
        #pragma unroll
        for (int p = 0; p < 4; p++) {
            uint32_t r4[4];
            unsigned rv = rV0 + ks * 16;
            unsigned addr = sV + (rv << 7) + ((((kgV0 + 2 * p) ^ (rv & 7))) << 4);
            ldm_x4t(r4, addr);
            uint32_t b0[2] = { r4[0], r4[1] };
            uint32_t b1[2] = { r4[2], r4[3] };
            mma_f16(o[2*p],   ap, b0);
            mma_f16(o[2*p+1], ap, b1);
        }
    }

    #pragma unroll
    for (int nt = 0; nt < 8; nt++) {
        const int d = 2 * t + 8 * nt;
        *(uint32_t*)(O + base + (size_t)r0 * EMB + d) =
            pack2(o[nt][0] * inv0, o[nt][1] * inv0);
        *(uint32_t*)(O + base + (size_t)r1 * EMB + d) =
            pack2(o[nt][2] * inv1, o[nt][3] * inv1);
    }
}

// ---------------------------------------------------------------------------
// ALL weight transposes in ONE launch: fp32 [K][N] -> fp16 K-major [N][K]
// ---------------------------------------------------------------------------
__global__ __launch_bounds__(256)
void transpose_all(const float* wv, const float* wk, const float* wq,
                   const float* wo, const float* w1, const float* w2,
                   __half* wvt, __half* wkt, __half* wqt,
                   __half* wot, __half* w1t, __half* w2t)
{
    __shared__ float tb[32][33];
    int bi = blockIdx.x;
    const float* in; __half* out; int K, N, li;
    if (bi < 1024) {
        K = EMB; N = EMB; li = bi & 255;
        int sel = bi >> 8;
        in  = sel == 0 ? wv  : sel == 1 ? wk  : sel == 2 ? wq  : wo;
        out = sel == 0 ? wvt : sel == 1 ? wkt : sel == 2 ? wqt : wot;
    } else if (bi < 1536) {
        K = EMB; N = FFD; li = bi - 1024; in = w1; out = w1t;
    } else {
        K = FFD; N = EMB; li = bi - 1536; in = w2; out = w2t;
    }
    const int nbx = K / 32;
    const int kb = (li % nbx) * 32, nb = (li / nbx) * 32;
    const int x = threadIdx.x & 31, y = (threadIdx.x >> 5) * 4;
    #pragma unroll
    for (int i = 0; i < 4; i++)
        tb[y + i][x] = in[(size_t)(kb + y + i) * N + nb + x];
    __syncthreads();
    #pragma unroll
    for (int i = 0; i < 4; i++)
        out[(size_t)(nb + y + i) * K + kb + x] = __float2half(tb[x][y + i]);
}

// ---------------------------------------------------------------------------
// convert 3 fp32 tensors to fp16
// ---------------------------------------------------------------------------
__global__ __launch_bounds__(256)
void cvt3(const float* __restrict__ a, const float* __restrict__ b,
          const float* __restrict__ c, __half* __restrict__ ha,
          __half* __restrict__ hb, __half* __restrict__ hc, int n4)
{
    int i = blockIdx.x * blockDim.x + threadIdx.x;
    if (i >= n4) return;
    float4 x;
    uint2 u;
    x = ((const float4*)a)[i];
    u.x = pack2(x.x, x.y); u.y = pack2(x.z, x.w);
    ((uint2*)ha)[i] = u;
    x = ((const float4*)b)[i];
    u.x = pack2(x.x, x.y); u.y = pack2(x.z, x.w);
    ((uint2*)hb)[i] = u;
    x = ((const float4*)c)[i];
    u.x = pack2(x.x, x.y); u.y = pack2(x.z, x.w);
    ((uint2*)hc)[i] = u;
}

// ---------------------------------------------------------------------------
// LN1: out16 = fp16( LN(half(A) + fp32 R) * g + b )   (no fp32 output)
// ---------------------------------------------------------------------------
__global__ __launch_bounds__(128)
void ln1_kernel(const __half* __restrict__ A, const float* __restrict__ R,
                const float* __restrict__ g, const float* __restrict__ b,
                __half* __restrict__ out16)
{
    __shared__ float red[8];
    const int row = blockIdx.x;
    const int t = threadIdx.x;
    const int lane = t & 31, w = t >> 5;

    uint2 au = ((const uint2*)(A + (size_t)row * EMB))[t];
    __half2 a0 = *(__half2*)&au.x, a1 = *(__half2*)&au.y;
    float4 y = ((const float4*)(R + (size_t)row * EMB))[t];
    float4 x;
    x.x = __low2float(a0)  + y.x;
    x.y = __high2float(a0) + y.y;
    x.z = __low2float(a1)  + y.z;
    x.w = __high2float(a1) + y.w;

    float s  = x.x + x.y + x.z + x.w;
    float sq = x.x * x.x + x.y * x.y + x.z * x.z + x.w * x.w;
    #pragma unroll
    for (int off = 16; off >= 1; off >>= 1) {
        s  += __shfl_xor_sync(0xffffffffu, s,  off);
        sq += __shfl_xor_sync(0xffffffffu, sq, off);
    }
    if (lane == 0) { red[w] = s; red[4 + w] = sq; }
    __syncthreads();
    float S  = red[0] + red[1] + red[2] + red[3];
    float SQ = red[4] + red[5] + red[6] + red[7];
    float mean = S * (1.f / EMB);
    float var  = SQ * (1.f / EMB) - mean * mean;
    float rstd = rsqrtf(var + 1e-5f);

    float4 gg = ((const float4*)g)[t];
    float4 bb = ((const float4*)b)[t];
    uint2 u;
    u.x = pack2((x.x - mean) * rstd * gg.x + bb.x,
                (x.y - mean) * rstd * gg.y + bb.y);
    u.y = pack2((x.z - mean) * rstd * gg.z + bb.z,
                (x.w - mean) * rstd * gg.w + bb.w);
    ((uint2*)(out16 + (size_t)row * EMB))[t] = u;
}

// ---------------------------------------------------------------------------
// LN2: out32 = LN(half(A) + half(R)) * g + b   (final fp32 output)
// ---------------------------------------------------------------------------
__global__ __launch_bounds__(128)
void ln2_kernel(const __half* __restrict__ A, const __half* __restrict__ R,
                const float* __restrict__ g, const float* __restrict__ b,
                float* __restrict__ out32)
{
    __shared__ float red[8];
    const int row = blockIdx.x;
    const int t = threadIdx.x;
    const int lane = t & 31, w = t >> 5;

    uint2 au = ((const uint2*)(A + (size_t)row * EMB))[t];
    uint2 ru = ((const uint2*)(R + (size_t)row * EMB))[t];
    __half2 a0 = *(__half2*)&au.x, a1 = *(__half2*)&au.y;
    __half2 r0 = *(__half2*)&ru.x, r1 = *(__half2*)&ru.y;
    float4 x;
    x.x = __low2float(a0)  + __low2float(r0);
    x.y = __high2float(a0) + __high2float(r0);
    x.z = __low2float(a1)  + __low2float(r1);
    x.w = __high2float(a1) + __high2float(r1);

    float s  = x.x + x.y + x.z + x.w;
    float sq = x.x * x.x + x.y * x.y + x.z * x.z + x.w * x.w;
    #pragma unroll
    for (int off = 16; off >= 1; off >>= 1) {
        s  += __shfl_xor_sync(0xffffffffu, s,  off);
        sq += __shfl_xor_sync(0xffffffffu, sq, off);
    }
    if (lane == 0) { red[w] = s; red[4 + w] = sq; }
    __syncthreads();
    float S  = red[0] + red[1] + red[2] + red[3];
    float SQ = red[4] + red[5] + red[6] + red[7];
    float mean = S * (1.f / EMB);
    float var  = SQ * (1.f / EMB) - mean * mean;
    float rstd = rsqrtf(var + 1e-5f);

    float4 gg = ((const float4*)g)[t];
    float4 bb = ((const float4*)b)[t];
    float4 o;
    o.x = (x.x - mean) * rstd * gg.x + bb.x;
    o.y = (x.y - mean) * rstd * gg.y + bb.y;
    o.z = (x.z - mean) * rstd * gg.z + bb.z;
    o.w = (x.w - mean) * rstd * gg.w + bb.w;
    ((float4*)(out32 + (size_t)row * EMB))[t] = o;
}

// ---------------------------------------------------------------------------
// Launch
// ---------------------------------------------------------------------------
extern "C" void kernel_launch(void* const* d_in, const int* in_sizes, int n_in,
                              void* d_out, int out_size)
{
    const float* value = (const float*)d_in[0];
    const float* key   = (const float*)d_in[1];
    const float* query = (const float*)d_in[2];
    const int*   mask  = (const int*)  d_in[3];
    const float* wv = (const float*)d_in[4];
    const float* bv = (const float*)d_in[5];
    const float* wk = (const float*)d_in[6];
    const float* bk = (const float*)d_in[7];
    const float* wq = (const float*)d_in[8];
    const float* bq = (const float*)d_in[9];
    const float* wo = (const float*)d_in[10];
    const float* bo = (const float*)d_in[11];
    const float* g1 = (const float*)d_in[12];
    const float* b1 = (const float*)d_in[13];
    const float* w1 = (const float*)d_in[14];
    const float* bf1 = (const float*)d_in[15];
    const float* w2 = (const float*)d_in[16];
    const float* bf2 = (const float*)d_in[17];
    const float* g2 = (const float*)d_in[18];
    const float* b2 = (const float*)d_in[19];
    float* out = (float*)d_out;

    __half *hval, *hkey, *hqry, *hq, *hk, *hv, *hatt, *hx, *hff, *ht1, *ht2;
    __half *wvt, *wkt, *wqt, *wot, *w1t, *w2t;
    cudaGetSymbolAddress((void**)&hval, h_val);
    cudaGetSymbolAddress((void**)&hkey, h_key);
    cudaGetSymbolAddress((void**)&hqry, h_qry);
    cudaGetSymbolAddress((void**)&hq,   h_q);
    cudaGetSymbolAddress((void**)&hk,   h_k);
    cudaGetSymbolAddress((void**)&hv,   h_v);
    cudaGetSymbolAddress((void**)&hatt, h_att);
    cudaGetSymbolAddress((void**)&hx,   h_x);
    cudaGetSymbolAddress((void**)&hff,  h_ff);
    cudaGetSymbolAddress((void**)&ht1,  h_t1);
    cudaGetSymbolAddress((void**)&ht2,  h_t2);
    cudaGetSymbolAddress((void**)&wvt,  g_wvt);
    cudaGetSymbolAddress((void**)&wkt,  g_wkt);
    cudaGetSymbolAddress((void**)&wqt,  g_wqt);
    cudaGetSymbolAddress((void**)&wot,  g_wot);
    cudaGetSymbolAddress((void**)&w1t,  g_w1t);
    cudaGetSymbolAddress((void**)&w2t,  g_w2t);

    cudaFuncSetAttribute(hgemm<1,0>,
        cudaFuncAttributeMaxDynamicSharedMemorySize, HG_SMEM);
    cudaFuncSetAttribute(hgemm<1,1>,
        cudaFuncAttributeMaxDynamicSharedMemorySize, HG_SMEM);
    cudaFuncSetAttribute(attn_h,
        cudaFuncAttributeMaxDynamicSharedMemorySize, ATT_SMEM);

    // fused weight transposes + input conversion
    transpose_all<<<2048, 256>>>(wv, wk, wq, wo, w1, w2,
                                 wvt, wkt, wqt, wot, w1t, w2t);
    {
        int n4 = MROWS * EMB / 4;
        cvt3<<<(n4 + 255) / 256, 256>>>(value, key, query, hval, hkey, hqry, n4);
    }

    dim3 gQKV(EMB / 128, MROWS / 128, 3);   // (4, 256, 3)
    dim3 gProj(EMB / 128, MROWS / 128, 1);
    dim3 gFF1 (FFD / 128, MROWS / 128, 1);
    dim3 gFF2 (EMB / 128, MROWS / 128, 1);

    // QKV projections batched into ONE launch
    {
        GemmArgs qa;
        qa.A[0] = hval; qa.A[1] = hkey; qa.A[2] = hqry;
        qa.B[0] = wvt;  qa.B[1] = wkt;  qa.B[2] = wqt;
        qa.bias[0] = bv; qa.bias[1] = bk; qa.bias[2] = bq;
        qa.C[0] = hv;   qa.C[1] = hk;   qa.C[2] = hq;
        hgemm<1,0><<<gQKV, 256, HG_SMEM>>>(qa, MROWS, EMB, EMB);
    }

    // block attention (fp16)
    dim3 gAtt(HEADS, ABLK, NB);
    attn_h<<<gAtt, 256, ATT_SMEM>>>(hq, hk, hv, mask, hatt);

    // output projection (fp16 out) + LN1 (fp16 out only)
    {
        GemmArgs oa = {};
        oa.A[0] = hatt; oa.B[0] = wot; oa.bias[0] = bo; oa.C[0] = ht1;
        hgemm<1,0><<<gProj, 256, HG_SMEM>>>(oa, MROWS, EMB, EMB);
    }
    ln1_kernel<<<MROWS, 128>>>(ht1, query, g1, b1, hx);

    // FFN + LN2
    {
        GemmArgs fa = {};
        fa.A[0] = hx; fa.B[0] = w1t; fa.bias[0] = bf1; fa.C[0] = hff;
        hgemm<1,1><<<gFF1, 256, HG_SMEM>>>(fa, MROWS, FFD, EMB);
    }
    {
        GemmArgs fb = {};
        fb.A[0] = hff; fb.B[0] = w2t; fb.bias[0] = bf2; fb.C[0] = ht2;
        hgemm<1,0><<<gFF2, 256, HG_SMEM>>>(fb, MROWS, EMB, FFD);
    }
    ln2_kernel<<<MROWS, 128>>>(ht2, hx, g2, b2, out);
}

// round 12
// speedup vs baseline: 1.6664x; 1.6664x over previous
#include <cuda_runtime.h>
#include <cuda_fp16.h>
#include <cstdint>
#include <cstdio>

// Problem constants
#define NB   4
#define LSEQ 8192
#define EMB  512
#define HEADS 8
#define HDIM 64
#define BS   128
#define ABLK 64
#define FFD  1024
#define MROWS (NB*LSEQ)  // 32768

// ---------------------------------------------------------------------------
// Scratch
// ---------------------------------------------------------------------------
__device__ __half h_val[MROWS * EMB];
__device__ __half h_key[MROWS * EMB];
__device__ __half h_qry[MROWS * EMB];
__device__ __half h_q  [MROWS * EMB];
__device__ __half h_k  [MROWS * EMB];
__device__ __half h_v  [MROWS * EMB];
__device__ __half h_att[MROWS * EMB];
__device__ __half h_x  [MROWS * EMB];
__device__ __half h_ff [MROWS * FFD];
__device__ __half h_t1 [MROWS * EMB];   // proj out (fp16)
__device__ __half h_t2 [MROWS * EMB];   // ff2 out (fp16)
// fp16 transposed weights (K-major [N][K])
__device__ __half g_wvt[EMB * EMB];
__device__ __half g_wkt[EMB * EMB];
__device__ __half g_wqt[EMB * EMB];
__device__ __half g_wot[EMB * EMB];
__device__ __half g_w1t[FFD * EMB];
__device__ __half g_w2t[EMB * FFD];

// ---------------------------------------------------------------------------
// helpers
// ---------------------------------------------------------------------------
__device__ __forceinline__ void cp16s(unsigned saddr, const void* src) {
    asm volatile("cp.async.cg.shared.global [%0], [%1], 16;" :: "r"(saddr), "l"(src));
}
#define CP_COMMIT() asm volatile("cp.async.commit_group;")
#define CP_WAIT0()  asm volatile("cp.async.wait_group 0;")
#define CP_WAIT1()  asm volatile("cp.async.wait_group 1;")

__device__ __forceinline__ unsigned smem_u32(const void* p) {
    return (unsigned)__cvta_generic_to_shared(p);
}

__device__ __forceinline__ void ldm_x4(uint32_t r[4], unsigned addr) {
    asm volatile("ldmatrix.sync.aligned.m8n8.x4.shared.b16 {%0,%1,%2,%3}, [%4];"
                 : "=r"(r[0]), "=r"(r[1]), "=r"(r[2]), "=r"(r[3]) : "r"(addr));
}
__device__ __forceinline__ void ldm_x4t(uint32_t r[4], unsigned addr) {
    asm volatile("ldmatrix.sync.aligned.m8n8.x4.trans.shared.b16 {%0,%1,%2,%3}, [%4];"
                 : "=r"(r[0]), "=r"(r[1]), "=r"(r[2]), "=r"(r[3]) : "r"(addr));
}

__device__ __forceinline__ void mma_f16(float c[4], const uint32_t a[4],
                                        const uint32_t b[2]) {
    asm volatile(
        "mma.sync.aligned.m16n8k16.row.col.f32.f16.f16.f32 "
        "{%0,%1,%2,%3}, {%4,%5,%6,%7}, {%8,%9}, {%0,%1,%2,%3};"
        : "+f"(c[0]), "+f"(c[1]), "+f"(c[2]), "+f"(c[3])
        : "r"(a[0]), "r"(a[1]), "r"(a[2]), "r"(a[3]), "r"(b[0]), "r"(b[1]));
}

__device__ __forceinline__ uint32_t pack2(float x, float y) {
    __half2 h = __floats2half2_rn(x, y);
    return *(uint32_t*)&h;
}

// ---------------------------------------------------------------------------
// FP16 tensor-core GEMM: CTA 128x128, 256 thr (8 warps 2x4), warp tile 64x32.
// BK=64 (SW128). 3-stage cp.async ring, one sync per chunk, 2 CTAs/SM.
// gridDim.z batches independent GEMMs (QKV).
// ---------------------------------------------------------------------------
#define HG_STAGE 32768
#define HG_SMEM  (3 * HG_STAGE)

struct GemmArgs {
    const __half* A[3];
    const __half* B[3];
    const float*  bias[3];
    void*         C[3];
};

template<int OUT_HALF, int DO_GELU>
__global__ __launch_bounds__(256, 2)
void hgemm(GemmArgs args, int M, int Nn, int K)
{
    extern __shared__ __align__(1024) char smem[];
    const unsigned sb = smem_u32(smem);

    const int z    = blockIdx.z;
    const int tid  = threadIdx.x;
    const int lane = tid & 31;
    const int warp = tid >> 5;
    const int wm   = warp >> 2;       // 0..1
    const int wn   = warp & 3;        // 0..3
    const int g    = lane >> 2;
    const int t    = lane & 3;

    const int m0 = blockIdx.y * 128;
    const int n0 = blockIdx.x * 128;
    const __half* Ag = args.A[z] + (size_t)m0 * K;
    const __half* Bg = args.B[z] + (size_t)n0 * K;
    const float* bias = args.bias[z];

    const unsigned rA = (unsigned)(wm * 64 + (lane & 7) + ((lane >> 3) & 1) * 8);
    const unsigned kgA0 = (unsigned)(lane >> 4);
    const unsigned rB = (unsigned)(wn * 32 + (lane & 7) + ((lane >> 4) & 1) * 8);
    const unsigned kgB0 = (unsigned)((lane >> 3) & 1);

    float acc[4][4][4];
    #pragma unroll
    for (int mt = 0; mt < 4; mt++)
        #pragma unroll
        for (int nt = 0; nt < 4; nt++)
            #pragma unroll
            for (int i = 0; i < 4; i++) acc[mt][nt][i] = 0.f;

    const int nCh = K / 64;

    auto load_chunk = [&](int s, int kc) {
        const unsigned sA = sb + s * HG_STAGE;
        const unsigned sB = sA + 16384;
        const __half* Ac = Ag + kc * 64;
        const __half* Bc = Bg + kc * 64;
        #pragma unroll
        for (int i = 0; i < 4; i++) {
            int id = tid + i * 256;          // 0..1023
            int r  = id >> 3;                // 0..127
            int kg = id & 7;
            unsigned off = (unsigned)(r * 128 + kg * 16);
            unsigned sw  = off ^ ((off >> 3) & 0x70);
            cp16s(sA + sw, Ac + (size_t)r * K + kg * 8);
            cp16s(sB + sw, Bc + (size_t)r * K + kg * 8);
        }
    };

    load_chunk(0, 0); CP_COMMIT();
    load_chunk(1, 1); CP_COMMIT();

    int s = 0;
    for (int c = 0; c < nCh; c++) {
        CP_WAIT1();
        __syncthreads();

        if (c + 2 < nCh) {
            int sn = s + 2; if (sn >= 3) sn -= 3;
            load_chunk(sn, c + 2);
        }
        CP_COMMIT();

        const unsigned sA = sb + s * HG_STAGE;
        const unsigned sB = sA + 16384;
        #pragma unroll
        for (int ks = 0; ks < 4; ks++) {
            uint32_t a[4][4];
            #pragma unroll
            for (int mt = 0; mt < 4; mt++) {
                unsigned r = rA + mt * 16;
                unsigned addr = sA + (r << 7) + ((((kgA0 + 2 * ks) ^ (r & 7))) << 4);
                ldm_x4(a[mt], addr);
            }
            uint32_t b[4][2];
            #pragma unroll
            for (int p = 0; p < 2; p++) {
                uint32_t r4[4];
                unsigned r = rB + p * 16;
                unsigned addr = sB + (r << 7) + ((((kgB0 + 2 * ks) ^ (r & 7))) << 4);
                ldm_x4(r4, addr);
                b[2*p][0]   = r4[0]; b[2*p][1]   = r4[1];
                b[2*p+1][0] = r4[2]; b[2*p+1][1] = r4[3];
            }
            #pragma unroll
            for (int mt = 0; mt < 4; mt++)
                #pragma unroll
                for (int nt = 0; nt < 4; nt++)
                    mma_f16(acc[mt][nt], a[mt], b[nt]);
        }

        if (++s >= 3) s = 0;
    }

    // epilogue
    #pragma unroll
    for (int nt = 0; nt < 4; nt++) {
        const int col = n0 + wn * 32 + nt * 8 + 2 * t;
        const float2 bv = *(const float2*)(bias + col);
        #pragma unroll
        for (int mt = 0; mt < 4; mt++) {
            const int row0 = m0 + wm * 64 + mt * 16 + g;
            const int row1 = row0 + 8;
            float v0 = acc[mt][nt][0] + bv.x;
            float v1 = acc[mt][nt][1] + bv.y;
            float v2 = acc[mt][nt][2] + bv.x;
            float v3 = acc[mt][nt][3] + bv.y;
            if (DO_GELU) {
                v0 = 0.5f * v0 * (1.f + erff(v0 * 0.70710678118654752f));
                v1 = 0.5f * v1 * (1.f + erff(v1 * 0.70710678118654752f));
                v2 = 0.5f * v2 * (1.f + erff(v2 * 0.70710678118654752f));
                v3 = 0.5f * v3 * (1.f + erff(v3 * 0.70710678118654752f));
            }
            if (OUT_HALF) {
                __half* C = (__half*)args.C[z];
                *(uint32_t*)(C + (size_t)row0 * Nn + col) = pack2(v0, v1);
                *(uint32_t*)(C + (size_t)row1 * Nn + col) = pack2(v2, v3);
            } else {
                float* C = (float*)args.C[z];
                *(float2*)(C + (size_t)row0 * Nn + col) = make_float2(v0, v1);
                *(float2*)(C + (size_t)row1 * Nn + col) = make_float2(v2, v3);
            }
        }
    }
}

// ---------------------------------------------------------------------------
// FP16 block-diagonal attention (R9 version: single cp.async group), 2 CTAs/SM
// ---------------------------------------------------------------------------
#define ATT_SMEM (3 * 16384)

__global__ __launch_bounds__(256, 2)
void attn_h(const __half* __restrict__ Q, const __half* __restrict__ K,
            const __half* __restrict__ V, const int* __restrict__ mask,
            __half* __restrict__ O)
{
    extern __shared__ __align__(1024) char smem[];
    const unsigned sQ = smem_u32(smem);
    const unsigned sK = sQ + 16384;
    const unsigned sV = sK + 16384;

    const int h = blockIdx.x, a = blockIdx.y, n = blockIdx.z;
    const int tid  = threadIdx.x;
    const int lane = tid & 31;
    const int w    = tid >> 5;
    const int g    = lane >> 2;
    const int t    = lane & 3;
    const size_t base = ((size_t)n * LSEQ + (size_t)a * BS) * EMB + h * HDIM;

    #pragma unroll
    for (int i = 0; i < 4; i++) {
        int id = tid + i * 256;
        int r  = id >> 3;
        int kg = id & 7;
        unsigned off = (unsigned)(r * 128 + kg * 16);
        unsigned sw  = off ^ ((off >> 3) & 0x70);
        const size_t go = base + (size_t)r * EMB + kg * 8;
        cp16s(sQ + sw, Q + go);
        cp16s(sK + sw, K + go);
        cp16s(sV + sw, V + go);
    }
    CP_COMMIT();
    CP_WAIT0();
    __syncthreads();

    float accs[16][4];
    #pragma unroll
    for (int nt = 0; nt < 16; nt++)
        #pragma unroll
        for (int i = 0; i < 4; i++) accs[nt][i] = 0.f;

    const unsigned rQ = (unsigned)(w * 16 + (lane & 7) + ((lane >> 3) & 1) * 8);
    const unsigned kgQ0 = (unsigned)(lane >> 4);
    const unsigned rK0 = (unsigned)((lane & 7) + ((lane >> 4) & 1) * 8);
    const unsigned kgK0 = (unsigned)((lane >> 3) & 1);

    #pragma unroll
    for (int ks = 0; ks < 4; ks++) {
        uint32_t aq[4];
        {
            unsigned addr = sQ + (rQ << 7) + ((((kgQ0 + 2 * ks) ^ (rQ & 7))) << 4);
            ldm_x4(aq, addr);
        }
        #pragma unroll
        for (int p = 0; p < 8; p++) {
            uint32_t r4[4];
            unsigned rKp = rK0 + p * 16;
            unsigned addr = sK + (rKp << 7) + ((((kgK0 + 2 * ks) ^ (rKp & 7))) << 4);
            ldm_x4(r4, addr);
            uint32_t b0[2] = { r4[0], r4[1] };
            uint32_t b1[2] = { r4[2], r4[3] };
            mma_f16(accs[2*p],   aq, b0);
            mma_f16(accs[2*p+1], aq, b1);
        }
    }

    const int* mrow = mask + n * (BS * BS);
    const int r0 = w * 16 + g;
    const int r1 = r0 + 8;
    float mx0 = -1e30f, mx1 = -1e30f;
    #pragma unroll
    for (int nt = 0; nt < 16; nt++) {
        const int c = 2 * t + 8 * nt;
        int2 m0v = *(const int2*)(mrow + (size_t)r0 * BS + c);
        int2 m1v = *(const int2*)(mrow + (size_t)r1 * BS + c);
        accs[nt][0] = m0v.x ? accs[nt][0] * 0.125f : -1e20f;
        accs[nt][1] = m0v.y ? accs[nt][1] * 0.125f : -1e20f;
        accs[nt][2] = m1v.x ? accs[nt][2] * 0.125f : -1e20f;
        accs[nt][3] = m1v.y ? accs[nt][3] * 0.125f : -1e20f;
        mx0 = fmaxf(mx0, fmaxf(accs[nt][0], accs[nt][1]));
        mx1 = fmaxf(mx1, fmaxf(accs[nt][2], accs[nt][3]));
    }
    #pragma unroll
    for (int off = 1; off <= 2; off <<= 1) {
        mx0 = fmaxf(mx0, __shfl_xor_sync(0xffffffffu, mx0, off));
        mx1 = fmaxf(mx1, __shfl_xor_sync(0xffffffffu, mx1, off));
    }
    float sum0 = 0.f, sum1 = 0.f;
    #pragma unroll
    for (int nt = 0; nt < 16; nt++) {
        accs[nt][0] = __expf(accs[nt][0] - mx0);
        accs[nt][1] = __expf(accs[nt][1] - mx0);
        accs[nt][2] = __expf(accs[nt][2] - mx1);
        accs[nt][3] = __expf(accs[nt][3] - mx1);
        sum0 += accs[nt][0] + accs[nt][1];
        sum1 += accs[nt][2] + accs[nt][3];
    }
    #pragma unroll
    for (int off = 1; off <= 2; off <<= 1) {
        sum0 += __shfl_xor_sync(0xffffffffu, sum0, off);
        sum1 += __shfl_xor_sync(0xffffffffu, sum1, off);
    }
    const float inv0 = 1.f / sum0;
    const float inv1 = 1.f / sum1;

    float o[8][4];
    #pragma unroll
    for (int nt = 0; nt < 8; nt++)
        #pragma unroll
        for (int i = 0; i < 4; i++) o[nt][i] = 0.f;

    const unsigned rV0 = (unsigned)((lane & 7) + ((lane >> 3) & 1) * 8);
    const unsigned kgV0 = (unsigned)(lane >> 4);

    #pragma unroll
    for (int ks = 0; ks < 8; ks++) {
        uint32_t ap[4];
        ap[0] = pack2(accs[2*ks][0],   accs[2*ks][1]);
        ap[1] = pack2(accs[2*ks][2],   accs[2*ks][3]);
        ap[2] = pack2(accs[2*ks+1][0], accs[2*ks+1][1]);
        ap[3] = pack2(accs[2*ks+1][2], accs[2*ks+1][3]);
        #pragma unroll
        for (int p = 0; p < 4; p++) {
            uint32_t r4[4];
            unsigned rv = rV0 + ks * 16;
            unsigned addr = sV + (rv << 7) + ((((kgV0 + 2 * p) ^ (rv & 7))) << 4);
            ldm_x4t(r4, addr);
            uint32_t b0[2] = { r4[0], r4[1] };
            uint32_t b1[2] = { r4[2], r4[3] };
            mma_f16(o[2*p],   ap, b0);
            mma_f16(o[2*p+1], ap, b1);
        }
    }

    #pragma unroll
    for (int nt = 0; nt < 8; nt++) {
        const int d = 2 * t + 8 * nt;
        *(uint32_t*)(O + base + (size_t)r0 * EMB + d) =
            pack2(o[nt][0] * inv0, o[nt][1] * inv0);
        *(uint32_t*)(O + base + (size_t)r1 * EMB + d) =
            pack2(o[nt][2] * inv1, o[nt][3] * inv1);
    }
}

// ---------------------------------------------------------------------------
// ALL weight transposes in ONE launch: fp32 [K][N] -> fp16 K-major [N][K]
// ---------------------------------------------------------------------------
__global__ __launch_bounds__(256)
void transpose_all(const float* wv, const float* wk, const float* wq,
                   const float* wo, const float* w1, const float* w2,
                   __half* wvt, __half* wkt, __half* wqt,
                   __half* wot, __half* w1t, __half* w2t)
{
    __shared__ float tb[32][33];
    int bi = blockIdx.x;
    const float* in; __half* out; int K, N, li;
    if (bi < 1024) {
        K = EMB; N = EMB; li = bi & 255;
        int sel = bi >> 8;
        in  = sel == 0 ? wv  : sel == 1 ? wk  : sel == 2 ? wq  : wo;
        out = sel == 0 ? wvt : sel == 1 ? wkt : sel == 2 ? wqt : wot;
    } else if (bi < 1536) {
        K = EMB; N = FFD; li = bi - 1024; in = w1; out = w1t;
    } else {
        K = FFD; N = EMB; li = bi - 1536; in = w2; out = w2t;
    }
    const int nbx = K / 32;
    const int kb = (li % nbx) * 32, nb = (li / nbx) * 32;
    const int x = threadIdx.x & 31, y = (threadIdx.x >> 5) * 4;
    #pragma unroll
    for (int i = 0; i < 4; i++)
        tb[y + i][x] = in[(size_t)(kb + y + i) * N + nb + x];
    __syncthreads();
    #pragma unroll
    for (int i = 0; i < 4; i++)
        out[(size_t)(nb + y + i) * K + kb + x] = __float2half(tb[x][y + i]);
}

// ---------------------------------------------------------------------------
// convert 3 fp32 tensors to fp16
// ---------------------------------------------------------------------------
__global__ __launch_bounds__(256)
void cvt3(const float* __restrict__ a, const float* __restrict__ b,
          const float* __restrict__ c, __half* __restrict__ ha,
          __half* __restrict__ hb, __half* __restrict__ hc, int n4)
{
    int i = blockIdx.x * blockDim.x + threadIdx.x;
    if (i >= n4) return;
    float4 x;
    uint2 u;
    x = ((const float4*)a)[i];
    u.x = pack2(x.x, x.y); u.y = pack2(x.z, x.w);
    ((uint2*)ha)[i] = u;
    x = ((const float4*)b)[i];
    u.x = pack2(x.x, x.y); u.y = pack2(x.z, x.w);
    ((uint2*)hb)[i] = u;
    x = ((const float4*)c)[i];
    u.x = pack2(x.x, x.y); u.y = pack2(x.z, x.w);
    ((uint2*)hc)[i] = u;
}

// ---------------------------------------------------------------------------
// LN1: out16 = fp16( LN(half(A) + fp32 R) * g + b )
// ---------------------------------------------------------------------------
__global__ __launch_bounds__(128)
void ln1_kernel(const __half* __restrict__ A, const float* __restrict__ R,
                const float* __restrict__ g, const float* __restrict__ b,
                __half* __restrict__ out16)
{
    __shared__ float red[8];
    const int row = blockIdx.x;
    const int t = threadIdx.x;
    const int lane = t & 31, w = t >> 5;

    uint2 au = ((const uint2*)(A + (size_t)row * EMB))[t];
    __half2 a0 = *(__half2*)&au.x, a1 = *(__half2*)&au.y;
    float4 y = ((const float4*)(R + (size_t)row * EMB))[t];
    float4 x;
    x.x = __low2float(a0)  + y.x;
    x.y = __high2float(a0) + y.y;
    x.z = __low2float(a1)  + y.z;
    x.w = __high2float(a1) + y.w;

    float s  = x.x + x.y + x.z + x.w;
    float sq = x.x * x.x + x.y * x.y + x.z * x.z + x.w * x.w;
    #pragma unroll
    for (int off = 16; off >= 1; off >>= 1) {
        s  += __shfl_xor_sync(0xffffffffu, s,  off);
        sq += __shfl_xor_sync(0xffffffffu, sq, off);
    }
    if (lane == 0) { red[w] = s; red[4 + w] = sq; }
    __syncthreads();
    float S  = red[0] + red[1] + red[2] + red[3];
    float SQ = red[4] + red[5] + red[6] + red[7];
    float mean = S * (1.f / EMB);
    float var  = SQ * (1.f / EMB) - mean * mean;
    float rstd = rsqrtf(var + 1e-5f);

    float4 gg = ((const float4*)g)[t];
    float4 bb = ((const float4*)b)[t];
    uint2 u;
    u.x = pack2((x.x - mean) * rstd * gg.x + bb.x,
                (x.y - mean) * rstd * gg.y + bb.y);
    u.y = pack2((x.z - mean) * rstd * gg.z + bb.z,
                (x.w - mean) * rstd * gg.w + bb.w);
    ((uint2*)(out16 + (size_t)row * EMB))[t] = u;
}

// ---------------------------------------------------------------------------
// LN2: out32 = LN(half(A) + half(R)) * g + b   (final fp32 output)
// ---------------------------------------------------------------------------
__global__ __launch_bounds__(128)
void ln2_kernel(const __half* __restrict__ A, const __half* __restrict__ R,
                const float* __restrict__ g, const float* __restrict__ b,
                float* __restrict__ out32)
{
    __shared__ float red[8];
    const int row = blockIdx.x;
    const int t = threadIdx.x;
    const int lane = t & 31, w = t >> 5;

    uint2 au = ((const uint2*)(A + (size_t)row * EMB))[t];
    uint2 ru = ((const uint2*)(R + (size_t)row * EMB))[t];
    __half2 a0 = *(__half2*)&au.x, a1 = *(__half2*)&au.y;
    __half2 r0 = *(__half2*)&ru.x, r1 = *(__half2*)&ru.y;
    float4 x;
    x.x = __low2float(a0)  + __low2float(r0);
    x.y = __high2float(a0) + __high2float(r0);
    x.z = __low2float(a1)  + __low2float(r1);
    x.w = __high2float(a1) + __high2float(r1);

    float s  = x.x + x.y + x.z + x.w;
    float sq = x.x * x.x + x.y * x.y + x.z * x.z + x.w * x.w;
    #pragma unroll
    for (int off = 16; off >= 1; off >>= 1) {
        s  += __shfl_xor_sync(0xffffffffu, s,  off);
        sq += __shfl_xor_sync(0xffffffffu, sq, off);
    }
    if (lane == 0) { red[w] = s; red[4 + w] = sq; }
    __syncthreads();
    float S  = red[0] + red[1] + red[2] + red[3];
    float SQ = red[4] + red[5] + red[6] + red[7];
    float mean = S * (1.f / EMB);
    float var  = SQ * (1.f / EMB) - mean * mean;
    float rstd = rsqrtf(var + 1e-5f);

    float4 gg = ((const float4*)g)[t];
    float4 bb = ((const float4*)b)[t];
    float4 o;
    o.x = (x.x - mean) * rstd * gg.x + bb.x;
    o.y = (x.y - mean) * rstd * gg.y + bb.y;
    o.z = (x.z - mean) * rstd * gg.z + bb.z;
    o.w = (x.w - mean) * rstd * gg.w + bb.w;
    ((float4*)(out32 + (size_t)row * EMB))[t] = o;
}

// ---------------------------------------------------------------------------
// Launch
// ---------------------------------------------------------------------------
extern "C" void kernel_launch(void* const* d_in, const int* in_sizes, int n_in,
                              void* d_out, int out_size)
{
    const float* value = (const float*)d_in[0];
    const float* key   = (const float*)d_in[1];
    const float* query = (const float*)d_in[2];
    const int*   mask  = (const int*)  d_in[3];
    const float* wv = (const float*)d_in[4];
    const float* bv = (const float*)d_in[5];
    const float* wk = (const float*)d_in[6];
    const float* bk = (const float*)d_in[7];
    const float* wq = (const float*)d_in[8];
    const float* bq = (const float*)d_in[9];
    const float* wo = (const float*)d_in[10];
    const float* bo = (const float*)d_in[11];
    const float* g1 = (const float*)d_in[12];
    const float* b1 = (const float*)d_in[13];
    const float* w1 = (const float*)d_in[14];
    const float* bf1 = (const float*)d_in[15];
    const float* w2 = (const float*)d_in[16];
    const float* bf2 = (const float*)d_in[17];
    const float* g2 = (const float*)d_in[18];
    const float* b2 = (const float*)d_in[19];
    float* out = (float*)d_out;

    __half *hval, *hkey, *hqry, *hq, *hk, *hv, *hatt, *hx, *hff, *ht1, *ht2;
    __half *wvt, *wkt, *wqt, *wot, *w1t, *w2t;
    cudaGetSymbolAddress((void**)&hval, h_val);
    cudaGetSymbolAddress((void**)&hkey, h_key);
    cudaGetSymbolAddress((void**)&hqry, h_qry);
    cudaGetSymbolAddress((void**)&hq,   h_q);
    cudaGetSymbolAddress((void**)&hk,   h_k);
    cudaGetSymbolAddress((void**)&hv,   h_v);
    cudaGetSymbolAddress((void**)&hatt, h_att);
    cudaGetSymbolAddress((void**)&hx,   h_x);
    cudaGetSymbolAddress((void**)&hff,  h_ff);
    cudaGetSymbolAddress((void**)&ht1,  h_t1);
    cudaGetSymbolAddress((void**)&ht2,  h_t2);
    cudaGetSymbolAddress((void**)&wvt,  g_wvt);
    cudaGetSymbolAddress((void**)&wkt,  g_wkt);
    cudaGetSymbolAddress((void**)&wqt,  g_wqt);
    cudaGetSymbolAddress((void**)&wot,  g_wot);
    cudaGetSymbolAddress((void**)&w1t,  g_w1t);
    cudaGetSymbolAddress((void**)&w2t,  g_w2t);

    cudaFuncSetAttribute(hgemm<1,0>,
        cudaFuncAttributeMaxDynamicSharedMemorySize, HG_SMEM);
    cudaFuncSetAttribute(hgemm<1,1>,
        cudaFuncAttributeMaxDynamicSharedMemorySize, HG_SMEM);
    cudaFuncSetAttribute(attn_h,
        cudaFuncAttributeMaxDynamicSharedMemorySize, ATT_SMEM);

    // fused weight transposes + input conversion
    transpose_all<<<2048, 256>>>(wv, wk, wq, wo, w1, w2,
                                 wvt, wkt, wqt, wot, w1t, w2t);
    {
        int n4 = MROWS * EMB / 4;
        cvt3<<<(n4 + 255) / 256, 256>>>(value, key, query, hval, hkey, hqry, n4);
    }

    dim3 gQKV(EMB / 128, MROWS / 128, 3);   // (4, 256, 3)
    dim3 gProj(EMB / 128, MROWS / 128, 1);
    dim3 gFF1 (FFD / 128, MROWS / 128, 1);
    dim3 gFF2 (EMB / 128, MROWS / 128, 1);

    // QKV projections batched into ONE launch
    {
        GemmArgs qa;
        qa.A[0] = hval; qa.A[1] = hkey; qa.A[2] = hqry;
        qa.B[0] = wvt;  qa.B[1] = wkt;  qa.B[2] = wqt;
        qa.bias[0] = bv; qa.bias[1] = bk; qa.bias[2] = bq;
        qa.C[0] = hv;   qa.C[1] = hk;   qa.C[2] = hq;
        hgemm<1,0><<<gQKV, 256, HG_SMEM>>>(qa, MROWS, EMB, EMB);
    }

    // block attention (fp16)
    dim3 gAtt(HEADS, ABLK, NB);
    attn_h<<<gAtt, 256, ATT_SMEM>>>(hq, hk, hv, mask, hatt);

    // output projection (fp16 out) + LN1 (fp16 out only)
    {
        GemmArgs oa = {};
        oa.A[0] = hatt; oa.B[0] = wot; oa.bias[0] = bo; oa.C[0] = ht1;
        hgemm<1,0><<<gProj, 256, HG_SMEM>>>(oa, MROWS, EMB, EMB);
    }
    ln1_kernel<<<MROWS, 128>>>(ht1, query, g1, b1, hx);

    // FFN + LN2
    {
        GemmArgs fa = {};
        fa.A[0] = hx; fa.B[0] = w1t; fa.bias[0] = bf1; fa.C[0] = hff;
        hgemm<1,1><<<gFF1, 256, HG_SMEM>>>(fa, MROWS, FFD, EMB);
    }
    {
        GemmArgs fb = {};
        fb.A[0] = hff; fb.B[0] = w2t; fb.bias[0] = bf2; fb.C[0] = ht2;
        hgemm<1,0><<<gFF2, 256, HG_SMEM>>>(fb, MROWS, EMB, FFD);
    }
    ln2_kernel<<<MROWS, 128>>>(ht2, hx, g2, b2, out);
}

// round 15
// speedup vs baseline: 1.7250x; 1.0352x over previous
#include <cuda_runtime.h>
#include <cuda_fp16.h>
#include <cstdint>
#include <cstdio>

// Problem constants
#define NB   4
#define LSEQ 8192
#define EMB  512
#define HEADS 8
#define HDIM 64
#define BS   128
#define ABLK 64
#define FFD  1024
#define MROWS (NB*LSEQ)  // 32768

// ---------------------------------------------------------------------------
// Scratch
// ---------------------------------------------------------------------------
__device__ __half h_val[MROWS * EMB];
__device__ __half h_key[MROWS * EMB];
__device__ __half h_qry[MROWS * EMB];
__device__ __half h_q  [MROWS * EMB];
__device__ __half h_k  [MROWS * EMB];
__device__ __half h_v  [MROWS * EMB];
__device__ __half h_att[MROWS * EMB];
__device__ __half h_x  [MROWS * EMB];
__device__ __half h_ff [MROWS * FFD];
__device__ __half h_t1 [MROWS * EMB];
__device__ __half h_t2 [MROWS * EMB];
// fp16 transposed weights (K-major [N][K])
__device__ __half g_wvt[EMB * EMB];
__device__ __half g_wkt[EMB * EMB];
__device__ __half g_wqt[EMB * EMB];
__device__ __half g_wot[EMB * EMB];
__device__ __half g_w1t[FFD * EMB];
__device__ __half g_w2t[EMB * FFD];

// ---------------------------------------------------------------------------
// helpers
// ---------------------------------------------------------------------------
__device__ __forceinline__ void cp16s(unsigned saddr, const void* src) {
    asm volatile("cp.async.cg.shared.global [%0], [%1], 16;" :: "r"(saddr), "l"(src));
}
#define CP_COMMIT() asm volatile("cp.async.commit_group;")
#define CP_WAIT0()  asm volatile("cp.async.wait_group 0;")
#define CP_WAIT1()  asm volatile("cp.async.wait_group 1;")

__device__ __forceinline__ unsigned smem_u32(const void* p) {
    return (unsigned)__cvta_generic_to_shared(p);
}

__device__ __forceinline__ void ldm_x4(uint32_t r[4], unsigned addr) {
    asm volatile("ldmatrix.sync.aligned.m8n8.x4.shared.b16 {%0,%1,%2,%3}, [%4];"
                 : "=r"(r[0]), "=r"(r[1]), "=r"(r[2]), "=r"(r[3]) : "r"(addr));
}
__device__ __forceinline__ void ldm_x4t(uint32_t r[4], unsigned addr) {
    asm volatile("ldmatrix.sync.aligned.m8n8.x4.trans.shared.b16 {%0,%1,%2,%3}, [%4];"
                 : "=r"(r[0]), "=r"(r[1]), "=r"(r[2]), "=r"(r[3]) : "r"(addr));
}

__device__ __forceinline__ void mma_f16(float c[4], const uint32_t a[4],
                                        const uint32_t b[2]) {
    asm volatile(
        "mma.sync.aligned.m16n8k16.row.col.f32.f16.f16.f32 "
        "{%0,%1,%2,%3}, {%4,%5,%6,%7}, {%8,%9}, {%0,%1,%2,%3};"
        : "+f"(c[0]), "+f"(c[1]), "+f"(c[2]), "+f"(c[3])
        : "r"(a[0]), "r"(a[1]), "r"(a[2]), "r"(a[3]), "r"(b[0]), "r"(b[1]));
}

__device__ __forceinline__ uint32_t pack2(float x, float y) {
    __half2 h = __floats2half2_rn(x, y);
    return *(uint32_t*)&h;
}

// ---------------------------------------------------------------------------
// FP16 tensor-core GEMM: CTA 128x128, 128 threads (4 warps 2x2),
// warp tile 64x64 (8 ldmatrix.x4 -> 32 MMAs per k-step).
// BK=64 (SW128). 3-stage cp.async ring, ONE sync per chunk, 2 CTAs/SM.
// gridDim.z batches independent GEMMs (QKV).
// ---------------------------------------------------------------------------
#define HG_STAGE 32768
#define HG_SMEM  (3 * HG_STAGE)

struct GemmArgs {
    const __half* A[3];
    const __half* B[3];
    const float*  bias[3];
    void*         C[3];
};

template<int OUT_HALF, int DO_GELU>
__global__ __launch_bounds__(128, 2)
void hgemm(GemmArgs args, int M, int Nn, int K)
{
    extern __shared__ __align__(1024) char smem[];
    const unsigned sb = smem_u32(smem);

    const int z    = blockIdx.z;
    const int tid  = threadIdx.x;
    const int lane = tid & 31;
    const int warp = tid >> 5;
    const int wm   = warp >> 1;       // 0..1 (64 rows)
    const int wn   = warp & 1;        // 0..1 (64 cols)
    const int g    = lane >> 2;
    const int t    = lane & 3;

    const int m0 = blockIdx.y * 128;
    const int n0 = blockIdx.x * 128;
    const __half* Ag = args.A[z] + (size_t)m0 * K;
    const __half* Bg = args.B[z] + (size_t)n0 * K;
    const float* bias = args.bias[z];

    const unsigned rA0  = (unsigned)(wm * 64 + (lane & 7) + ((lane >> 3) & 1) * 8);
    const unsigned kgA0 = (unsigned)(lane >> 4);
    const unsigned rB0  = (unsigned)(wn * 64 + (lane & 7) + ((lane >> 4) & 1) * 8);
    const unsigned kgB0 = (unsigned)((lane >> 3) & 1);

    float acc[4][8][4];
    #pragma unroll
    for (int mt = 0; mt < 4; mt++)
        #pragma unroll
        for (int nt = 0; nt < 8; nt++)
            #pragma unroll
            for (int i = 0; i < 4; i++) acc[mt][nt][i] = 0.f;

    const int nCh = K / 64;

    auto load_chunk = [&](int s, int kc) {
        const unsigned sA = sb + s * HG_STAGE;
        const unsigned sB = sA + 16384;
        const __half* Ac = Ag + kc * 64;
        const __half* Bc = Bg + kc * 64;
        #pragma unroll
        for (int i = 0; i < 8; i++) {
            int id = tid + i * 128;          // 0..1023
            int r  = id >> 3;                // 0..127
            int kg = id & 7;
            unsigned off = (unsigned)(r * 128 + kg * 16);
            unsigned sw  = off ^ ((off >> 3) & 0x70);
            cp16s(sA + sw, Ac + (size_t)r * K + kg * 8);
            cp16s(sB + sw, Bc + (size_t)r * K + kg * 8);
        }
    };

    load_chunk(0, 0); CP_COMMIT();
    load_chunk(1, 1); CP_COMMIT();

    int s = 0;
    for (int c = 0; c < nCh; c++) {
        CP_WAIT1();
        __syncthreads();

        if (c + 2 < nCh) {
            int sn = s + 2; if (sn >= 3) sn -= 3;
            load_chunk(sn, c + 2);
        }
        CP_COMMIT();

        const unsigned sA = sb + s * HG_STAGE;
        const unsigned sB = sA + 16384;
        #pragma unroll
        for (int ks = 0; ks < 4; ks++) {
            uint32_t a[4][4];
            #pragma unroll
            for (int mt = 0; mt < 4; mt++) {
                unsigned r = rA0 + mt * 16;
                unsigned addr = sA + (r << 7) + ((((kgA0 + 2 * ks) ^ (r & 7))) << 4);
                ldm_x4(a[mt], addr);
            }
            uint32_t b[8][2];
            #pragma unroll
            for (int p = 0; p < 4; p++) {
                uint32_t r4[4];
                unsigned r = rB0 + p * 16;
                unsigned addr = sB + (r << 7) + ((((kgB0 + 2 * ks) ^ (r & 7))) << 4);
                ldm_x4(r4, addr);
                b[2*p][0]   = r4[0]; b[2*p][1]   = r4[1];
                b[2*p+1][0] = r4[2]; b[2*p+1][1] = r4[3];
            }
            #pragma unroll
            for (int mt = 0; mt < 4; mt++)
                #pragma unroll
                for (int nt = 0; nt < 8; nt++)
                    mma_f16(acc[mt][nt], a[mt], b[nt]);
        }

        if (++s >= 3) s = 0;
    }

    // epilogue
    #pragma unroll
    for (int nt = 0; nt < 8; nt++) {
        const int col = n0 + wn * 64 + nt * 8 + 2 * t;
        const float2 bv = *(const float2*)(bias + col);
        #pragma unroll
        for (int mt = 0; mt < 4; mt++) {
            const int row0 = m0 + wm * 64 + mt * 16 + g;
            const int row1 = row0 + 8;
            float v0 = acc[mt][nt][0] + bv.x;
            float v1 = acc[mt][nt][1] + bv.y;
            float v2 = acc[mt][nt][2] + bv.x;
            float v3 = acc[mt][nt][3] + bv.y;
            if (DO_GELU) {
                v0 = 0.5f * v0 * (1.f + erff(v0 * 0.70710678118654752f));
                v1 = 0.5f * v1 * (1.f + erff(v1 * 0.70710678118654752f));
                v2 = 0.5f * v2 * (1.f + erff(v2 * 0.70710678118654752f));
                v3 = 0.5f * v3 * (1.f + erff(v3 * 0.70710678118654752f));
            }
            if (OUT_HALF) {
                __half* C = (__half*)args.C[z];
                *(uint32_t*)(C + (size_t)row0 * Nn + col) = pack2(v0, v1);
                *(uint32_t*)(C + (size_t)row1 * Nn + col) = pack2(v2, v3);
            } else {
                float* C = (float*)args.C[z];
                *(float2*)(C + (size_t)row0 * Nn + col) = make_float2(v0, v1);
                *(float2*)(C + (size_t)row1 * Nn + col) = make_float2(v2, v3);
            }
        }
    }
}

// ---------------------------------------------------------------------------
// FP16 block-diagonal attention (R9/R12 version), 2 CTAs/SM
// ---------------------------------------------------------------------------
#define ATT_SMEM (3 * 16384)

__global__ __launch_bounds__(256, 2)
void attn_h(const __half* __restrict__ Q, const __half* __restrict__ K,
            const __half* __restrict__ V, const int* __restrict__ mask,
            __half* __restrict__ O)
{
    extern __shared__ __align__(1024) char smem[];
    const unsigned sQ = smem_u32(smem);
    const unsigned sK = sQ + 16384;
    const unsigned sV = sK + 16384;

    const int h = blockIdx.x, a = blockIdx.y, n = blockIdx.z;
    const int tid  = threadIdx.x;
    const int lane = tid & 31;
    const int w    = tid >> 5;
    const int g    = lane >> 2;
    const int t    = lane & 3;
    const size_t base = ((size_t)n * LSEQ + (size_t)a * BS) * EMB + h * HDIM;

    #pragma unroll
    for (int i = 0; i < 4; i++) {
        int id = tid + i * 256;
        int r  = id >> 3;
        int kg = id & 7;
        unsigned off = (unsigned)(r * 128 + kg * 16);
        unsigned sw  = off ^ ((off >> 3) & 0x70);
        const size_t go = base + (size_t)r * EMB + kg * 8;
        cp16s(sQ + sw, Q + go);
        cp16s(sK + sw, K + go);
        cp16s(sV + sw, V + go);
    }
    CP_COMMIT();
    CP_WAIT0();
    __syncthreads();

    float accs[16][4];
    #pragma unroll
    for (int nt = 0; nt < 16; nt++)
        #pragma unroll
        for (int i = 0; i < 4; i++) accs[nt][i] = 0.f;

    const unsigned rQ = (unsigned)(w * 16 + (lane & 7) + ((lane >> 3) & 1) * 8);
    const unsigned kgQ0 = (unsigned)(lane >> 4);
    const unsigned rK0 = (unsigned)((lane & 7) + ((lane >> 4) & 1) * 8);
    const unsigned kgK0 = (unsigned)((lane >> 3) & 1);

    #pragma unroll
    for (int ks = 0; ks < 4; ks++) {
        uint32_t aq[4];
        {
            unsigned addr = sQ + (rQ << 7) + ((((kgQ0 + 2 * ks) ^ (rQ & 7))) << 4);
            ldm_x4(aq, addr);
        }
        #pragma unroll
        for (int p = 0; p < 8; p++) {
            uint32_t r4[4];
            unsigned rKp = rK0 + p * 16;
            unsigned addr = sK + (rKp << 7) + ((((kgK0 + 2 * ks) ^ (rKp & 7))) << 4);
            ldm_x4(r4, addr);
            uint32_t b0[2] = { r4[0], r4[1] };
            uint32_t b1[2] = { r4[2], r4[3] };
            mma_f16(accs[2*p],   aq, b0);
            mma_f16(accs[2*p+1], aq, b1);
        }
    }

    const int* mrow = mask + n * (BS * BS);
    const int r0 = w * 16 + g;
    const int r1 = r0 + 8;
    float mx0 = -1e30f, mx1 = -1e30f;
    #pragma unroll
    for (int nt = 0; nt < 16; nt++) {
        const int c = 2 * t + 8 * nt;
        int2 m0v = *(const int2*)(mrow + (size_t)r0 * BS + c);
        int2 m1v = *(const int2*)(mrow + (size_t)r1 * BS + c);
        accs[nt][0] = m0v.x ? accs[nt][0] * 0.125f : -1e20f;
        accs[nt][1] = m0v.y ? accs[nt][1] * 0.125f : -1e20f;
        accs[nt][2] = m1v.x ? accs[nt][2] * 0.125f : -1e20f;
        accs[nt][3] = m1v.y ? accs[nt][3] * 0.125f : -1e20f;
        mx0 = fmaxf(mx0, fmaxf(accs[nt][0], accs[nt][1]));
        mx1 = fmaxf(mx1, fmaxf(accs[nt][2], accs[nt][3]));
    }
    #pragma unroll
    for (int off = 1; off <= 2; off <<= 1) {
        mx0 = fmaxf(mx0, __shfl_xor_sync(0xffffffffu, mx0, off));
        mx1 = fmaxf(mx1, __shfl_xor_sync(0xffffffffu, mx1, off));
    }
    float sum0 = 0.f, sum1 = 0.f;
    #pragma unroll
    for (int nt = 0; nt < 16; nt++) {
        accs[nt][0] = __expf(accs[nt][0] - mx0);
        accs[nt][1] = __expf(accs[nt][1] - mx0);
        accs[nt][2] = __expf(accs[nt][2] - mx1);
        accs[nt][3] = __expf(accs[nt][3] - mx1);
        sum0 += accs[nt][0] + accs[nt][1];
        sum1 += accs[nt][2] + accs[nt][3];
    }
    #pragma unroll
    for (int off = 1; off <= 2; off <<= 1) {
        sum0 += __shfl_xor_sync(0xffffffffu, sum0, off);
        sum1 += __shfl_xor_sync(0xffffffffu, sum1, off);
    }
    const float inv0 = 1.f / sum0;
    const float inv1 = 1.f / sum1;

    float o[8][4];
    #pragma unroll
    for (int nt = 0; nt < 8; nt++)
        #pragma unroll
        for (int i = 0; i < 4; i++) o[nt][i] = 0.f;

    const unsigned rV0 = (unsigned)((lane & 7) + ((lane >> 3) & 1) * 8);
    const unsigned kgV0 = (unsigned)(lane >> 4);

    #pragma unroll
    for (int ks = 0; ks < 8; ks++) {
        uint32_t ap[4];
        ap[0] = pack2(accs[2*ks][0],   accs[2*ks][1]);
        ap[1] = pack2(accs[2*ks][2],   accs[2*ks][3]);
        ap[2] = pack2(accs[2*ks+1][0], accs[2*ks+1][1]);
        ap[3] = pack2(accs[2*ks+1][2], accs[2*ks+1][3]);
        #pragma unroll
        for (int p = 0; p < 4; p++) {
            uint32_t r4[4];
            unsigned rv = rV0 + ks * 16;
            unsigned addr = sV + (rv << 7) + ((((kgV0 + 2 * p) ^ (rv & 7))) << 4);
            ldm_x4t(r4, addr);
            uint32_t b0[2] = { r4[0], r4[1] };
            uint32_t b1[2] = { r4[2], r4[3] };
            mma_f16(o[2*p],   ap, b0);
            mma_f16(o[2*p+1], ap, b1);
        }
    }

    #pragma unroll
    for (int nt = 0; nt < 8; nt++) {
        const int d = 2 * t + 8 * nt;
        *(uint32_t*)(O + base + (size_t)r0 * EMB + d) =
            pack2(o[nt][0] * inv0, o[nt][1] * inv0);
        *(uint32_t*)(O + base + (size_t)r1 * EMB + d) =
            pack2(o[nt][2] * inv1, o[nt][3] * inv1);
    }
}

// ---------------------------------------------------------------------------
// ALL weight transposes in ONE launch: fp32 [K][N] -> fp16 K-major [N][K]
// ---------------------------------------------------------------------------
__global__ __launch_bounds__(256)
void transpose_all(const float* wv, const float* wk, const float* wq,
                   const float* wo, const float* w1, const float* w2,
                   __half* wvt, __half* wkt, __half* wqt,
                   __half* wot, __half* w1t, __half* w2t)
{
    __shared__ float tb[32][33];
    int bi = blockIdx.x;
    const float* in; __half* out; int K, N, li;
    if (bi < 1024) {
        K = EMB; N = EMB; li = bi & 255;
        int sel = bi >> 8;
        in  = sel == 0 ? wv  : sel == 1 ? wk  : sel == 2 ? wq  : wo;
        out = sel == 0 ? wvt : sel == 1 ? wkt : sel == 2 ? wqt : wot;
    } else if (bi < 1536) {
        K = EMB; N = FFD; li = bi - 1024; in = w1; out = w1t;
    } else {
        K = FFD; N = EMB; li = bi - 1536; in = w2; out = w2t;
    }
    const int nbx = K / 32;
    const int kb = (li % nbx) * 32, nb = (li / nbx) * 32;
    const int x = threadIdx.x & 31, y = (threadIdx.x >> 5) * 4;
    #pragma unroll
    for (int i = 0; i < 4; i++)
        tb[y + i][x] = in[(size_t)(kb + y + i) * N + nb + x];
    __syncthreads();
    #pragma unroll
    for (int i = 0; i < 4; i++)
        out[(size_t)(nb + y + i) * K + kb + x] = __float2half(tb[x][y + i]);
}

// ---------------------------------------------------------------------------
// convert 3 fp32 tensors to fp16
// ---------------------------------------------------------------------------
__global__ __launch_bounds__(256)
void cvt3(const float* __restrict__ a, const float* __restrict__ b,
          const float* __restrict__ c, __half* __restrict__ ha,
          __half* __restrict__ hb, __half* __restrict__ hc, int n4)
{
    int i = blockIdx.x * blockDim.x + threadIdx.x;
    if (i >= n4) return;
    float4 x;
    uint2 u;
    x = ((const float4*)a)[i];
    u.x = pack2(x.x, x.y); u.y = pack2(x.z, x.w);
    ((uint2*)ha)[i] = u;
    x = ((const float4*)b)[i];
    u.x = pack2(x.x, x.y); u.y = pack2(x.z, x.w);
    ((uint2*)hb)[i] = u;
    x = ((const float4*)c)[i];
    u.x = pack2(x.x, x.y); u.y = pack2(x.z, x.w);
    ((uint2*)hc)[i] = u;
}

// ---------------------------------------------------------------------------
// LN1: out16 = fp16( LN(half(A) + half(R)) * g + b )   (fp16 residual)
// ---------------------------------------------------------------------------
__global__ __launch_bounds__(128)
void ln1_kernel(const __half* __restrict__ A, const __half* __restrict__ R,
                const float* __restrict__ g, const float* __restrict__ b,
                __half* __restrict__ out16)
{
    __shared__ float red[8];
    const int row = blockIdx.x;
    const int t = threadIdx.x;
    const int lane = t & 31, w = t >> 5;

    uint2 au = ((const uint2*)(A + (size_t)row * EMB))[t];
    uint2 ru = ((const uint2*)(R + (size_t)row * EMB))[t];
    __half2 a0 = *(__half2*)&au.x, a1 = *(__half2*)&au.y;
    __half2 r0 = *(__half2*)&ru.x, r1 = *(__half2*)&ru.y;
    float4 x;
    x.x = __low2float(a0)  + __low2float(r0);
    x.y = __high2float(a0) + __high2float(r0);
    x.z = __low2float(a1)  + __low2float(r1);
    x.w = __high2float(a1) + __high2float(r1);

    float s  = x.x + x.y + x.z + x.w;
    float sq = x.x * x.x + x.y * x.y + x.z * x.z + x.w * x.w;
    #pragma unroll
    for (int off = 16; off >= 1; off >>= 1) {
        s  += __shfl_xor_sync(0xffffffffu, s,  off);
        sq += __shfl_xor_sync(0xffffffffu, sq, off);
    }
    if (lane == 0) { red[w] = s; red[4 + w] = sq; }
    __syncthreads();
    float S  = red[0] + red[1] + red[2] + red[3];
    float SQ = red[4] + red[5] + red[6] + red[7];
    float mean = S * (1.f / EMB);
    float var  = SQ * (1.f / EMB) - mean * mean;
    float rstd = rsqrtf(var + 1e-5f);

    float4 gg = ((const float4*)g)[t];
    float4 bb = ((const float4*)b)[t];
    uint2 u;
    u.x = pack2((x.x - mean) * rstd * gg.x + bb.x,
                (x.y - mean) * rstd * gg.y + bb.y);
    u.y = pack2((x.z - mean) * rstd * gg.z + bb.z,
                (x.w - mean) * rstd * gg.w + bb.w);
    ((uint2*)(out16 + (size_t)row * EMB))[t] = u;
}

// ---------------------------------------------------------------------------
// LN2: out32 = LN(half(A) + half(R)) * g + b   (final fp32 output)
// ---------------------------------------------------------------------------
__global__ __launch_bounds__(128)
void ln2_kernel(const __half* __restrict__ A, const __half* __restrict__ R,
                const float* __restrict__ g, const float* __restrict__ b,
                float* __restrict__ out32)
{
    __shared__ float red[8];
    const int row = blockIdx.x;
    const int t = threadIdx.x;
    const int lane = t & 31, w = t >> 5;

    uint2 au = ((const uint2*)(A + (size_t)row * EMB))[t];
    uint2 ru = ((const uint2*)(R + (size_t)row * EMB))[t];
    __half2 a0 = *(__half2*)&au.x, a1 = *(__half2*)&au.y;
    __half2 r0 = *(__half2*)&ru.x, r1 = *(__half2*)&ru.y;
    float4 x;
    x.x = __low2float(a0)  + __low2float(r0);
    x.y = __high2float(a0) + __high2float(r0);
    x.z = __low2float(a1)  + __low2float(r1);
    x.w = __high2float(a1) + __high2float(r1);

    float s  = x.x + x.y + x.z + x.w;
    float sq = x.x * x.x + x.y * x.y + x.z * x.z + x.w * x.w;
    #pragma unroll
    for (int off = 16; off >= 1; off >>= 1) {
        s  += __shfl_xor_sync(0xffffffffu, s,  off);
        sq += __shfl_xor_sync(0xffffffffu, sq, off);
    }
    if (lane == 0) { red[w] = s; red[4 + w] = sq; }
    __syncthreads();
    float S  = red[0] + red[1] + red[2] + red[3];
    float SQ = red[4] + red[5] + red[6] + red[7];
    float mean = S * (1.f / EMB);
    float var  = SQ * (1.f / EMB) - mean * mean;
    float rstd = rsqrtf(var + 1e-5f);

    float4 gg = ((const float4*)g)[t];
    float4 bb = ((const float4*)b)[t];
    float4 o;
    o.x = (x.x - mean) * rstd * gg.x + bb.x;
    o.y = (x.y - mean) * rstd * gg.y + bb.y;
    o.z = (x.z - mean) * rstd * gg.z + bb.z;
    o.w = (x.w - mean) * rstd * gg.w + bb.w;
    ((float4*)(out32 + (size_t)row * EMB))[t] = o;
}

// ---------------------------------------------------------------------------
// Launch
// ---------------------------------------------------------------------------
extern "C" void kernel_launch(void* const* d_in, const int* in_sizes, int n_in,
                              void* d_out, int out_size)
{
    const float* value = (const float*)d_in[0];
    const float* key   = (const float*)d_in[1];
    const float* query = (const float*)d_in[2];
    const int*   mask  = (const int*)  d_in[3];
    const float* wv = (const float*)d_in[4];
    const float* bv = (const float*)d_in[5];
    const float* wk = (const float*)d_in[6];
    const float* bk = (const float*)d_in[7];
    const float* wq = (const float*)d_in[8];
    const float* bq = (const float*)d_in[9];
    const float* wo = (const float*)d_in[10];
    const float* bo = (const float*)d_in[11];
    const float* g1 = (const float*)d_in[12];
    const float* b1 = (const float*)d_in[13];
    const float* w1 = (const float*)d_in[14];
    const float* bf1 = (const float*)d_in[15];
    const float* w2 = (const float*)d_in[16];
    const float* bf2 = (const float*)d_in[17];
    const float* g2 = (const float*)d_in[18];
    const float* b2 = (const float*)d_in[19];
    float* out = (float*)d_out;

    __half *hval, *hkey, *hqry, *hq, *hk, *hv, *hatt, *hx, *hff, *ht1, *ht2;
    __half *wvt, *wkt, *wqt, *wot, *w1t, *w2t;
    cudaGetSymbolAddress((void**)&hval, h_val);
    cudaGetSymbolAddress((void**)&hkey, h_key);
    cudaGetSymbolAddress((void**)&hqry, h_qry);
    cudaGetSymbolAddress((void**)&hq,   h_q);
    cudaGetSymbolAddress((void**)&hk,   h_k);
    cudaGetSymbolAddress((void**)&hv,   h_v);
    cudaGetSymbolAddress((void**)&hatt, h_att);
    cudaGetSymbolAddress((void**)&hx,   h_x);
    cudaGetSymbolAddress((void**)&hff,  h_ff);
    cudaGetSymbolAddress((void**)&ht1,  h_t1);
    cudaGetSymbolAddress((void**)&ht2,  h_t2);
    cudaGetSymbolAddress((void**)&wvt,  g_wvt);
    cudaGetSymbolAddress((void**)&wkt,  g_wkt);
    cudaGetSymbolAddress((void**)&wqt,  g_wqt);
    cudaGetSymbolAddress((void**)&wot,  g_wot);
    cudaGetSymbolAddress((void**)&w1t,  g_w1t);
    cudaGetSymbolAddress((void**)&w2t,  g_w2t);

    cudaFuncSetAttribute(hgemm<1,0>,
        cudaFuncAttributeMaxDynamicSharedMemorySize, HG_SMEM);
    cudaFuncSetAttribute(hgemm<1,1>,
        cudaFuncAttributeMaxDynamicSharedMemorySize, HG_SMEM);
    cudaFuncSetAttribute(attn_h,
        cudaFuncAttributeMaxDynamicSharedMemorySize, ATT_SMEM);

    // fused weight transposes + input conversion
    transpose_all<<<2048, 256>>>(wv, wk, wq, wo, w1, w2,
                                 wvt, wkt, wqt, wot, w1t, w2t);
    {
        int n4 = MROWS * EMB / 4;
        cvt3<<<(n4 + 255) / 256, 256>>>(value, key, query, hval, hkey, hqry, n4);
    }

    dim3 gQKV(EMB / 128, MROWS / 128, 3);   // (4, 256, 3)
    dim3 gProj(EMB / 128, MROWS / 128, 1);
    dim3 gFF1 (FFD / 128, MROWS / 128, 1);
    dim3 gFF2 (EMB / 128, MROWS / 128, 1);

    // QKV projections batched into ONE launch
    {
        GemmArgs qa;
        qa.A[0] = hval; qa.A[1] = hkey; qa.A[2] = hqry;
        qa.B[0] = wvt;  qa.B[1] = wkt;  qa.B[2] = wqt;
        qa.bias[0] = bv; qa.bias[1] = bk; qa.bias[2] = bq;
        qa.C[0] = hv;   qa.C[1] = hk;   qa.C[2] = hq;
        hgemm<1,0><<<gQKV, 128, HG_SMEM>>>(qa, MROWS, EMB, EMB);
    }

    // block attention (fp16)
    dim3 gAtt(HEADS, ABLK, NB);
    attn_h<<<gAtt, 256, ATT_SMEM>>>(hq, hk, hv, mask, hatt);

    // output projection (fp16 out) + LN1 (fp16 residual from hqry)
    {
        GemmArgs oa = {};
        oa.A[0] = hatt; oa.B[0] = wot; oa.bias[0] = bo; oa.C[0] = ht1;
        hgemm<1,0><<<gProj, 128, HG_SMEM>>>(oa, MROWS, EMB, EMB);
    }
    ln1_kernel<<<MROWS, 128>>>(ht1, hqry, g1, b1, hx);

    // FFN + LN2
    {
        GemmArgs fa = {};
        fa.A[0] = hx; fa.B[0] = w1t; fa.bias[0] = bf1; fa.C[0] = hff;
        hgemm<1,1><<<gFF1, 128, HG_SMEM>>>(fa, MROWS, FFD, EMB);
    }
    {
        GemmArgs fb = {};
        fb.A[0] = hff; fb.B[0] = w2t; fb.bias[0] = bf2; fb.C[0] = ht2;
        hgemm<1,0><<<gFF2, 128, HG_SMEM>>>(fb, MROWS, EMB, FFD);
    }
    ln2_kernel<<<MROWS, 128>>>(ht2, hx, g2, b2, out);
}